// round 10
// baseline (speedup 1.0000x reference)
#include <cuda_runtime.h>
#include <cuda_fp16.h>
#include <cstdint>
#include <math.h>

#define T_TOK 4096
#define HDIM  2048
#define NEXP  16
#define FDIM  768
#define TOPK  4

#define BM    128
#define BN    256                       // B rows per tile
#define ROWB  144                       // 128B data + 16B pad per smem row
#define ATILE (128 * ROWB)              // 18432 B (A region; B starts here)
#define STG   (384 * ROWB)              // 55296 B per stage (A 128 + B 256 rows)
#define NSTG  3
#define SMEM_GEMM (1024 + NSTG * STG)   // 166912 B -> 1 block/SM
#define REX   132                       // exchange row stride (floats); mult of 4 for float4 alignment

// ---- scratch (device globals; allocation is forbidden) ----
__device__ int    g_counts[NEXP];
__device__ int    g_tok[NEXP * T_TOK];
__device__ float  g_w[NEXP * T_TOK];
__device__ int    g_eid[T_TOK * TOPK];
__device__ float  g_topw[T_TOK * TOPK];
__device__ __half g_x16[(size_t)T_TOK * HDIM];
__device__ __half g_wg16[(size_t)NEXP * FDIM * HDIM];
__device__ __half g_wu16[(size_t)NEXP * FDIM * HDIM];
__device__ __half g_wd16[(size_t)NEXP * HDIM * FDIM];
__device__ __half g_act16[(size_t)NEXP * T_TOK * FDIM];

// ---------------------------------------------------------------------------
// helpers
// ---------------------------------------------------------------------------
__device__ __forceinline__ uint32_t smem_u32(const void* p) {
    uint32_t a;
    asm("{ .reg .u64 t; cvta.to.shared.u64 t, %1; cvt.u32.u64 %0, t; }" : "=r"(a) : "l"(p));
    return a;
}
__device__ __forceinline__ void cp16(uint32_t smem, const void* g) {
    asm volatile("cp.async.cg.shared.global [%0], [%1], 16;" :: "r"(smem), "l"(g));
}
__device__ __forceinline__ void cp_commit() { asm volatile("cp.async.commit_group;"); }
template <int N>
__device__ __forceinline__ void cp_wait() { asm volatile("cp.async.wait_group %0;" :: "n"(N)); }

#define MMA_F16(C, A0, A1, A2, A3, B0, B1) \
    asm volatile("mma.sync.aligned.m16n8k16.row.col.f32.f16.f16.f32 " \
                 "{%0,%1,%2,%3}, {%4,%5,%6,%7}, {%8,%9}, {%0,%1,%2,%3};" \
                 : "+f"((C)[0]), "+f"((C)[1]), "+f"((C)[2]), "+f"((C)[3]) \
                 : "r"(A0), "r"(A1), "r"(A2), "r"(A3), "r"(B0), "r"(B1))

#define LDSM4(R, addr) \
    asm volatile("ldmatrix.sync.aligned.m8n8.x4.shared.b16 {%0,%1,%2,%3}, [%4];" \
                 : "=r"((R)[0]), "=r"((R)[1]), "=r"((R)[2]), "=r"((R)[3]) : "r"(addr))

__device__ __forceinline__ void cvt_store4(const float4 v, __half* dst) {
    __half2 a = __floats2half2_rn(v.x, v.y);
    __half2 b = __floats2half2_rn(v.z, v.w);
    uint2 u = make_uint2(*(const uint32_t*)&a, *(const uint32_t*)&b);
    *(uint2*)dst = u;
}

// ---------------------------------------------------------------------------
// prep: fp32 -> fp16 for Wg/Wu/Wd; zero out; zero counts
// ---------------------------------------------------------------------------
__global__ void prep_kernel(const float4* __restrict__ Wg,
                            const float4* __restrict__ Wu,
                            const float4* __restrict__ Wd,
                            float4* __restrict__ out) {
    size_t i0 = (size_t)blockIdx.x * blockDim.x + threadIdx.x;
    size_t st = (size_t)gridDim.x * blockDim.x;
    const size_t nx4 = (size_t)T_TOK * HDIM / 4;
    const size_t nw4 = (size_t)NEXP * FDIM * HDIM / 4;
    const float4 z = make_float4(0.f, 0.f, 0.f, 0.f);
    for (size_t i = i0; i < nx4; i += st) out[i] = z;
    for (size_t i = i0; i < nw4; i += st) {
        cvt_store4(Wg[i], g_wg16 + 4 * i);
        cvt_store4(Wu[i], g_wu16 + 4 * i);
        cvt_store4(Wd[i], g_wd16 + 4 * i);
    }
    if (i0 < NEXP) g_counts[i0] = 0;
}

// ---------------------------------------------------------------------------
// Router: 16 tokens/block; also emits fp16 copy of x.
// ---------------------------------------------------------------------------
#define RT_TOKS 16
#define RT_PAD  2052
#define RT_SMEM ((RT_TOKS * RT_PAD + RT_TOKS * NEXP) * 4)

__global__ __launch_bounds__(256) void router_kernel(const float* __restrict__ x,
                                                     const float* __restrict__ Wr) {
    extern __shared__ float rs[];
    float* xs = rs;
    float* lg = rs + RT_TOKS * RT_PAD;
    int tid = threadIdx.x;
    int tok0 = blockIdx.x * RT_TOKS;

    for (int idx = tid; idx < RT_TOKS * HDIM; idx += 256) {
        int t = idx >> 11, k = idx & (HDIM - 1);
        xs[t * RT_PAD + k] = x[(size_t)(tok0 + t) * HDIM + k];
    }
    __syncthreads();

    for (int idx = tid * 4; idx < RT_TOKS * HDIM; idx += 256 * 4) {
        int t = idx >> 11, k = idx & (HDIM - 1);
        float4 v = *(const float4*)(xs + t * RT_PAD + k);
        cvt_store4(v, g_x16 + (size_t)(tok0 + t) * HDIM + k);
    }

    int t = tid & 15, e = tid >> 4;
    const float* wr = Wr + (size_t)e * HDIM;
    const float* xr = xs + t * RT_PAD;
    float acc = 0.0f;
#pragma unroll 8
    for (int k = 0; k < HDIM; k++) acc += xr[k] * wr[k];
    lg[t * NEXP + e] = acc;
    __syncthreads();

    if (tid < RT_TOKS) {
        int tt = tok0 + tid;
        const float* l = lg + tid * NEXP;
        float m = l[0];
#pragma unroll
        for (int i = 1; i < NEXP; i++) m = fmaxf(m, l[i]);
        float p[NEXP]; float s = 0.0f;
#pragma unroll
        for (int i = 0; i < NEXP; i++) { p[i] = expf(l[i] - m); s += p[i]; }
        float inv_s = 1.0f / s;
        bool used[NEXP];
#pragma unroll
        for (int i = 0; i < NEXP; i++) used[i] = false;
        int ids[TOPK]; float ws[TOPK]; float wsum = 0.0f;
#pragma unroll
        for (int k = 0; k < TOPK; k++) {
            int bi = -1; float bv = -1.0f;
#pragma unroll
            for (int i = 0; i < NEXP; i++)
                if (!used[i] && p[i] > bv) { bv = p[i]; bi = i; }
            used[bi] = true;
            ids[k] = bi; ws[k] = bv * inv_s; wsum += ws[k];
        }
        float inv_w = 1.0f / wsum;
#pragma unroll
        for (int k = 0; k < TOPK; k++) {
            g_eid[tt * TOPK + k]  = ids[k];
            g_topw[tt * TOPK + k] = ws[k] * inv_w;
        }
    }
}

__global__ void dispatch_kernel() {
    int i = blockIdx.x * blockDim.x + threadIdx.x;
    if (i >= T_TOK * TOPK) return;
    int e = g_eid[i];
    int pos = atomicAdd(&g_counts[e], 1);
    g_tok[e * T_TOK + pos] = i >> 2;
    g_w[e * T_TOK + pos]   = g_topw[i];
}

// ---------------------------------------------------------------------------
// Mainloop: BM=128, BN=256, BK=64 halves (128B). 512 threads, 16 warps of
// 32x64. 3-stage cp.async ring, ldmatrix.x4 fragments.
// Per thread per stage: 6 x cp16 — one 16B column chunk at rows r0+64k.
// ---------------------------------------------------------------------------
struct Frag { float acc[2][8][4]; };

__device__ __forceinline__ void mainloop(uint32_t sb1,
                                         const char* asrc0, const char* asrc1,
                                         const char* bsrc0, const char* bsrc1,
                                         uint32_t RS, uint32_t dstb, int NIT,
                                         int wm, int wc, int lane, Frag& F) {
    auto issue = [&](int s, int kb) {
        uint32_t d0 = sb1 + s * STG + dstb;
        cp16(d0,              asrc0 + kb);
        cp16(d0 +  64 * ROWB, asrc1 + kb);
        cp16(d0 + 128 * ROWB, bsrc0 + kb);
        cp16(d0 + 192 * ROWB, bsrc0 + 64 * RS + kb);
        cp16(d0 + 256 * ROWB, bsrc1 + kb);
        cp16(d0 + 320 * ROWB, bsrc1 + 64 * RS + kb);
    };

    uint32_t a_lane = (uint32_t)((lane & 15) * ROWB + (lane >> 4) * 16);
    uint32_t b_lane = (uint32_t)(((lane >> 4) * 8 + (lane & 7)) * ROWB + ((lane >> 3) & 1) * 16);
    uint32_t aoff0 = (uint32_t)(wm * 32 * ROWB) + a_lane;
    uint32_t aoff1 = aoff0 + 16 * ROWB;
    uint32_t boff  = ATILE + (uint32_t)(wc * 64 * ROWB) + b_lane;

    issue(0, 0);   cp_commit();
    issue(1, 128); cp_commit();

    for (int it = 0; it < NIT; ++it) {
        cp_wait<1>();
        __syncthreads();
        int pf = it + 2;
        if (pf < NIT) issue(pf % 3, pf * 128);
        cp_commit();

        uint32_t base = sb1 + (it % 3) * STG;
#pragma unroll
        for (int ks = 0; ks < 4; ks++) {
            uint32_t ko = ks * 32;
            uint32_t a0[4], a1[4];
            LDSM4(a0, base + aoff0 + ko);
            LDSM4(a1, base + aoff1 + ko);
#pragma unroll
            for (int np = 0; np < 4; np++) {
                uint32_t b[4];
                LDSM4(b, base + boff + np * (16 * ROWB) + ko);
                MMA_F16(F.acc[0][2 * np],     a0[0], a0[1], a0[2], a0[3], b[0], b[1]);
                MMA_F16(F.acc[0][2 * np + 1], a0[0], a0[1], a0[2], a0[3], b[2], b[3]);
                MMA_F16(F.acc[1][2 * np],     a1[0], a1[1], a1[2], a1[3], b[0], b[1]);
                MMA_F16(F.acc[1][2 * np + 1], a1[0], a1[1], a1[2], a1[3], b[2], b[3]);
            }
        }
    }
}

// ---------------------------------------------------------------------------
// GEMM1: 128 gate cols + 128 up cols per block. grid (32, 6, 16), 512 thr.
// ---------------------------------------------------------------------------
__global__ __launch_bounds__(512, 1) void gemm1_kernel() {
    extern __shared__ char smem[];
    int e = blockIdx.z;
    int cnt = g_counts[e];
    int m0 = blockIdx.x * BM;
    if (m0 >= cnt) return;
    int n0 = blockIdx.y * 128;
    int tid = threadIdx.x;

    int* toks = (int*)smem;
    if (tid < BM) {
        int m = m0 + tid;
        toks[tid] = (m < cnt) ? g_tok[e * T_TOK + m] : g_tok[e * T_TOK];
    }
    __syncthreads();

    uint32_t sb1 = smem_u32(smem) + 1024;
    int r = tid >> 3, c = tid & 7;
    const char* asrc0 = (const char*)(g_x16 + (size_t)toks[r] * HDIM) + c * 16;
    const char* asrc1 = (const char*)(g_x16 + (size_t)toks[r + 64] * HDIM) + c * 16;
    const char* bsrc0 = (const char*)(g_wg16 + ((size_t)e * FDIM + n0 + r) * HDIM) + c * 16;
    const char* bsrc1 = (const char*)(g_wu16 + ((size_t)e * FDIM + n0 + r) * HDIM) + c * 16;
    uint32_t dstb = (uint32_t)(r * ROWB + c * 16);

    int wid = tid >> 5, lane = tid & 31;
    int wm = wid & 3, wc = wid >> 2;          // wc 0,1 = gate; 2,3 = up

    Frag F = {};
    mainloop(sb1, asrc0, asrc1, bsrc0, bsrc1, HDIM * 2, dstb,
             HDIM * 2 / 128, wm, wc, lane, F);

    // exchange gate/up halves, SiLU combine, store fp16 act
    __syncthreads();
    float* ex = (float*)(smem + 1024);
    float* eu = ex + 128 * REX;
    float* dbuf = (wc < 2) ? ex : eu;
    int cb0 = (wc & 1) * 64;
    int qr = lane >> 2, qc = lane & 3;
#pragma unroll
    for (int mi = 0; mi < 2; mi++) {
        int rr = wm * 32 + mi * 16 + qr;
#pragma unroll
        for (int ni = 0; ni < 8; ni++) {
            int col = cb0 + ni * 8 + qc * 2;
            *(float2*)&dbuf[rr * REX + col]       = make_float2(F.acc[mi][ni][0], F.acc[mi][ni][1]);
            *(float2*)&dbuf[(rr + 8) * REX + col] = make_float2(F.acc[mi][ni][2], F.acc[mi][ni][3]);
        }
    }
    __syncthreads();

    int rr = tid >> 2, cb = (tid & 3) * 32;
    int m = m0 + rr;
    if (m < cnt) {
        float rw = g_w[e * T_TOK + m];
        __half* dst = g_act16 + ((size_t)e * T_TOK + m) * FDIM + n0 + cb;
        const float* gg = ex + rr * REX + cb;
        const float* uu = eu + rr * REX + cb;
#pragma unroll
        for (int j = 0; j < 32; j += 4) {
            float4 g4 = *(const float4*)(gg + j);
            float4 u4 = *(const float4*)(uu + j);
            float4 v;
            v.x = g4.x / (1.0f + expf(-g4.x)) * u4.x * rw;
            v.y = g4.y / (1.0f + expf(-g4.y)) * u4.y * rw;
            v.z = g4.z / (1.0f + expf(-g4.z)) * u4.z * rw;
            v.w = g4.w / (1.0f + expf(-g4.w)) * u4.w * rw;
            cvt_store4(v, dst + j);
        }
    }
}

// ---------------------------------------------------------------------------
// GEMM2: out[tok] += act16 @ Wd16^T, BN=256, K=768. grid (32, 8, 16), 512 thr.
// ---------------------------------------------------------------------------
__global__ __launch_bounds__(512, 1) void gemm2_kernel(float* __restrict__ out) {
    extern __shared__ char smem[];
    int e = blockIdx.z;
    int cnt = g_counts[e];
    int m0 = blockIdx.x * BM;
    if (m0 >= cnt) return;
    int n0 = blockIdx.y * BN;
    int tid = threadIdx.x;

    int* toks = (int*)smem;
    if (tid < BM) {
        int m = m0 + tid;
        toks[tid] = (m < cnt) ? g_tok[e * T_TOK + m] : g_tok[e * T_TOK];
    }
    __syncthreads();

    uint32_t sb1 = smem_u32(smem) + 1024;
    int r = tid >> 3, c = tid & 7;
    const char* asrc0 = (const char*)(g_act16 + ((size_t)e * T_TOK + m0 + r) * FDIM) + c * 16;
    const char* asrc1 = asrc0 + (size_t)64 * FDIM * 2;
    const char* bsrc0 = (const char*)(g_wd16 + ((size_t)e * HDIM + n0 + r) * FDIM) + c * 16;
    const char* bsrc1 = bsrc0 + (size_t)128 * FDIM * 2;
    uint32_t dstb = (uint32_t)(r * ROWB + c * 16);

    int wid = tid >> 5, lane = tid & 31;
    int wm = wid & 3, wn = wid >> 2;
    int qr = lane >> 2, qc = lane & 3;

    Frag F = {};
    mainloop(sb1, asrc0, asrc1, bsrc0, bsrc1, FDIM * 2, dstb,
             FDIM * 2 / 128, wm, wn, lane, F);

    // scatter-add epilogue (f32x2 RED)
#pragma unroll
    for (int mi = 0; mi < 2; mi++) {
#pragma unroll
        for (int rh = 0; rh < 2; rh++) {
            int mrow = wm * 32 + mi * 16 + rh * 8 + qr;
            int m = m0 + mrow;
            if (m < cnt) {
                float* dst = out + (size_t)toks[mrow] * HDIM + n0 + wn * 64;
#pragma unroll
                for (int ni = 0; ni < 8; ni++) {
                    float2 v = make_float2(F.acc[mi][ni][rh * 2 + 0], F.acc[mi][ni][rh * 2 + 1]);
                    atomicAdd(reinterpret_cast<float2*>(dst + ni * 8 + qc * 2), v);
                }
            }
        }
    }
}

// ---------------------------------------------------------------------------
extern "C" void kernel_launch(void* const* d_in, const int* in_sizes, int n_in,
                              void* d_out, int out_size) {
    const float* x  = (const float*)d_in[0];
    const float* Wr = (const float*)d_in[1];
    const float* Wg = (const float*)d_in[2];
    const float* Wu = (const float*)d_in[3];
    const float* Wd = (const float*)d_in[4];
    float* out = (float*)d_out;

    cudaFuncSetAttribute(router_kernel, cudaFuncAttributeMaxDynamicSharedMemorySize, RT_SMEM);
    cudaFuncSetAttribute(gemm1_kernel,  cudaFuncAttributeMaxDynamicSharedMemorySize, SMEM_GEMM);
    cudaFuncSetAttribute(gemm2_kernel,  cudaFuncAttributeMaxDynamicSharedMemorySize, SMEM_GEMM);

    prep_kernel<<<1024, 256>>>((const float4*)Wg, (const float4*)Wu,
                               (const float4*)Wd, (float4*)out);

    router_kernel<<<T_TOK / RT_TOKS, 256, RT_SMEM>>>(x, Wr);

    dispatch_kernel<<<(T_TOK * TOPK + 255) / 256, 256>>>();

    dim3 g1(T_TOK / BM, FDIM / 128, NEXP);
    gemm1_kernel<<<g1, 512, SMEM_GEMM>>>();

    dim3 g2(T_TOK / BM, HDIM / BN, NEXP);
    gemm2_kernel<<<g2, 512, SMEM_GEMM>>>(out);
}

// round 11
// speedup vs baseline: 1.0981x; 1.0981x over previous
#include <cuda_runtime.h>
#include <cuda_fp16.h>
#include <cstdint>
#include <math.h>

#define T_TOK 4096
#define HDIM  2048
#define NEXP  16
#define FDIM  768
#define TOPK  4

#define BM    128
#define ROWB  144                       // 128B data + 16B pad per smem row
#define TILEB (128 * ROWB)              // 18432 B per matrix tile
#define STG   (2 * TILEB)               // 36864 B per stage (A + B)
#define NSTG  3
#define SMEM_GEMM (1024 + NSTG * STG)   // 111616 B -> 2 blocks/SM

// ticket-scavenged side work inside gemm1: Wd cvt + out zero
#define WD_F4   ((NEXP * HDIM * FDIM) / 4)        // 6291456 / ... = 6.29M float4
#define OUT_F4  ((T_TOK * HDIM) / 4)              // 2.10M float4
#define CHUNK_F4 8192                             // 256 thr * 32 float4 per ticket
#define NT_WD   (WD_F4 / CHUNK_F4)                // 768
#define NT_OUT  (OUT_F4 / CHUNK_F4)               // 256
#define NTICK   (NT_WD + NT_OUT)                  // 1024

// ---- scratch (device globals; allocation is forbidden) ----
__device__ int    g_counts[NEXP];
__device__ int    g_ticket;
__device__ int    g_tok[NEXP * T_TOK];
__device__ float  g_w[NEXP * T_TOK];
__device__ int    g_eid[T_TOK * TOPK];
__device__ float  g_topw[T_TOK * TOPK];
__device__ __half g_x16[(size_t)T_TOK * HDIM];
__device__ __half g_wg16[(size_t)NEXP * FDIM * HDIM];
__device__ __half g_wu16[(size_t)NEXP * FDIM * HDIM];
__device__ __half g_wd16[(size_t)NEXP * HDIM * FDIM];
__device__ __half g_act16[(size_t)NEXP * T_TOK * FDIM];

// ---------------------------------------------------------------------------
// helpers
// ---------------------------------------------------------------------------
__device__ __forceinline__ uint32_t smem_u32(const void* p) {
    uint32_t a;
    asm("{ .reg .u64 t; cvta.to.shared.u64 t, %1; cvt.u32.u64 %0, t; }" : "=r"(a) : "l"(p));
    return a;
}
__device__ __forceinline__ void cp16(uint32_t smem, const void* g) {
    asm volatile("cp.async.cg.shared.global [%0], [%1], 16;" :: "r"(smem), "l"(g));
}
__device__ __forceinline__ void cp_commit() { asm volatile("cp.async.commit_group;"); }
template <int N>
__device__ __forceinline__ void cp_wait() { asm volatile("cp.async.wait_group %0;" :: "n"(N)); }

#define MMA_F16(C, A0, A1, A2, A3, B0, B1) \
    asm volatile("mma.sync.aligned.m16n8k16.row.col.f32.f16.f16.f32 " \
                 "{%0,%1,%2,%3}, {%4,%5,%6,%7}, {%8,%9}, {%0,%1,%2,%3};" \
                 : "+f"((C)[0]), "+f"((C)[1]), "+f"((C)[2]), "+f"((C)[3]) \
                 : "r"(A0), "r"(A1), "r"(A2), "r"(A3), "r"(B0), "r"(B1))

#define LDSM4(R, addr) \
    asm volatile("ldmatrix.sync.aligned.m8n8.x4.shared.b16 {%0,%1,%2,%3}, [%4];" \
                 : "=r"((R)[0]), "=r"((R)[1]), "=r"((R)[2]), "=r"((R)[3]) : "r"(addr))

__device__ __forceinline__ void cvt_store4(const float4 v, __half* dst) {
    __half2 a = __floats2half2_rn(v.x, v.y);
    __half2 b = __floats2half2_rn(v.z, v.w);
    uint2 u = make_uint2(*(const uint32_t*)&a, *(const uint32_t*)&b);
    *(uint2*)dst = u;
}

// ---------------------------------------------------------------------------
// prep: fp32 -> fp16 for Wg/Wu only; reset counts + ticket.
// (Wd conversion + out zeroing are scavenged by gemm1's idle blocks.)
// ---------------------------------------------------------------------------
__global__ void prep_kernel(const float4* __restrict__ Wg,
                            const float4* __restrict__ Wu) {
    size_t i0 = (size_t)blockIdx.x * blockDim.x + threadIdx.x;
    size_t st = (size_t)gridDim.x * blockDim.x;
    const size_t nw4 = (size_t)NEXP * FDIM * HDIM / 4;
    for (size_t i = i0; i < nw4; i += st) {
        cvt_store4(Wg[i], g_wg16 + 4 * i);
        cvt_store4(Wu[i], g_wu16 + 4 * i);
    }
    if (i0 < NEXP) g_counts[i0] = 0;
    if (i0 == 0)  g_ticket = 0;
}

// ---------------------------------------------------------------------------
// Router: 16 tokens/block; also emits fp16 copy of x.
// ---------------------------------------------------------------------------
#define RT_TOKS 16
#define RT_PAD  2052
#define RT_SMEM ((RT_TOKS * RT_PAD + RT_TOKS * NEXP) * 4)

__global__ __launch_bounds__(256) void router_kernel(const float* __restrict__ x,
                                                     const float* __restrict__ Wr) {
    extern __shared__ float rs[];
    float* xs = rs;
    float* lg = rs + RT_TOKS * RT_PAD;
    int tid = threadIdx.x;
    int tok0 = blockIdx.x * RT_TOKS;

    for (int idx = tid; idx < RT_TOKS * HDIM; idx += 256) {
        int t = idx >> 11, k = idx & (HDIM - 1);
        xs[t * RT_PAD + k] = x[(size_t)(tok0 + t) * HDIM + k];
    }
    __syncthreads();

    for (int idx = tid * 4; idx < RT_TOKS * HDIM; idx += 256 * 4) {
        int t = idx >> 11, k = idx & (HDIM - 1);
        float4 v = *(const float4*)(xs + t * RT_PAD + k);
        cvt_store4(v, g_x16 + (size_t)(tok0 + t) * HDIM + k);
    }

    int t = tid & 15, e = tid >> 4;
    const float* wr = Wr + (size_t)e * HDIM;
    const float* xr = xs + t * RT_PAD;
    float acc = 0.0f;
#pragma unroll 8
    for (int k = 0; k < HDIM; k++) acc += xr[k] * wr[k];
    lg[t * NEXP + e] = acc;
    __syncthreads();

    if (tid < RT_TOKS) {
        int tt = tok0 + tid;
        const float* l = lg + tid * NEXP;
        float m = l[0];
#pragma unroll
        for (int i = 1; i < NEXP; i++) m = fmaxf(m, l[i]);
        float p[NEXP]; float s = 0.0f;
#pragma unroll
        for (int i = 0; i < NEXP; i++) { p[i] = expf(l[i] - m); s += p[i]; }
        float inv_s = 1.0f / s;
        bool used[NEXP];
#pragma unroll
        for (int i = 0; i < NEXP; i++) used[i] = false;
        int ids[TOPK]; float ws[TOPK]; float wsum = 0.0f;
#pragma unroll
        for (int k = 0; k < TOPK; k++) {
            int bi = -1; float bv = -1.0f;
#pragma unroll
            for (int i = 0; i < NEXP; i++)
                if (!used[i] && p[i] > bv) { bv = p[i]; bi = i; }
            used[bi] = true;
            ids[k] = bi; ws[k] = bv * inv_s; wsum += ws[k];
        }
        float inv_w = 1.0f / wsum;
#pragma unroll
        for (int k = 0; k < TOPK; k++) {
            g_eid[tt * TOPK + k]  = ids[k];
            g_topw[tt * TOPK + k] = ws[k] * inv_w;
        }
    }
}

__global__ void dispatch_kernel() {
    int i = blockIdx.x * blockDim.x + threadIdx.x;
    if (i >= T_TOK * TOPK) return;
    int e = g_eid[i];
    int pos = atomicAdd(&g_counts[e], 1);
    g_tok[e * T_TOK + pos] = i >> 2;
    g_w[e * T_TOK + pos]   = g_topw[i];
}

// ---------------------------------------------------------------------------
// Ticket drain: Wd f32->fp16 conversion + out zeroing, claimed in 128KB
// chunks by gemm1 blocks (idle blocks immediately; compute blocks after
// their epilogue). Deterministic output; all tickets complete before the
// gemm1 kernel can finish.
// ---------------------------------------------------------------------------
__device__ __forceinline__ void drain_tickets(const float4* __restrict__ Wd,
                                              float4* __restrict__ out,
                                              int tid) {
    __shared__ int tk;
    for (;;) {
        if (tid == 0) tk = atomicAdd(&g_ticket, 1);
        __syncthreads();
        int t = tk;
        __syncthreads();
        if (t >= NTICK) return;
        if (t < NT_WD) {
            size_t base = (size_t)t * CHUNK_F4 + tid * 32;
#pragma unroll 8
            for (int j = 0; j < 32; j++)
                cvt_store4(Wd[base + j], g_wd16 + 4 * (base + j));
        } else {
            size_t base = (size_t)(t - NT_WD) * CHUNK_F4 + tid * 32;
            const float4 z = make_float4(0.f, 0.f, 0.f, 0.f);
#pragma unroll 8
            for (int j = 0; j < 32; j++)
                out[base + j] = z;
        }
    }
}

// ---------------------------------------------------------------------------
// GEMM mainloop core, BK=64, 3-stage cp.async ring, ldmatrix.x4 fragments.
// 8 warps, each 32 (rows) x 64 (cols).
// ---------------------------------------------------------------------------
struct Frag { float acc[2][8][4]; };

__device__ __forceinline__ void mainloop(char* smem, uint32_t sb1,
                                         const char* asrc, const char* bsrc,
                                         uint32_t adst_off, int NIT,
                                         int wm, int wcol, int lane, Frag& F) {
    auto issue = [&](int s, int kb) {
        uint32_t a0 = sb1 + s * STG + adst_off;
#pragma unroll
        for (int j = 0; j < 4; j++) cp16(a0 + j * 16, asrc + kb + j * 16);
        uint32_t b0 = a0 + TILEB;
#pragma unroll
        for (int j = 0; j < 4; j++) cp16(b0 + j * 16, bsrc + kb + j * 16);
    };

    uint32_t a_lane = (uint32_t)((lane & 15) * ROWB + (lane >> 4) * 16);
    uint32_t b_lane = (uint32_t)(((lane >> 4) * 8 + (lane & 7)) * ROWB + ((lane >> 3) & 1) * 16);
    uint32_t aoff0 = (uint32_t)(wm * 32 * ROWB) + a_lane;
    uint32_t aoff1 = aoff0 + 16 * ROWB;
    uint32_t boff  = TILEB + (uint32_t)(wcol * 64 * ROWB) + b_lane;

    issue(0, 0);   cp_commit();
    issue(1, 128); cp_commit();

    for (int it = 0; it < NIT; ++it) {
        cp_wait<1>();
        __syncthreads();
        int pf = it + 2;
        if (pf < NIT) issue(pf % 3, pf * 128);
        cp_commit();

        uint32_t base = sb1 + (it % 3) * STG;
#pragma unroll
        for (int ks = 0; ks < 4; ks++) {
            uint32_t ko = ks * 32;
            uint32_t a0[4], a1[4];
            LDSM4(a0, base + aoff0 + ko);
            LDSM4(a1, base + aoff1 + ko);
#pragma unroll
            for (int np = 0; np < 4; np++) {
                uint32_t b[4];
                LDSM4(b, base + boff + np * (16 * ROWB) + ko);
                MMA_F16(F.acc[0][2 * np],     a0[0], a0[1], a0[2], a0[3], b[0], b[1]);
                MMA_F16(F.acc[0][2 * np + 1], a0[0], a0[1], a0[2], a0[3], b[2], b[3]);
                MMA_F16(F.acc[1][2 * np],     a1[0], a1[1], a1[2], a1[3], b[0], b[1]);
                MMA_F16(F.acc[1][2 * np + 1], a1[0], a1[1], a1[2], a1[3], b[2], b[3]);
            }
        }
    }
}

// ---------------------------------------------------------------------------
// GEMM1: gate cols 64 + up cols 64 per block; SiLU combine via smem exchange.
// Idle blocks + finished blocks scavenge Wd conversion / out zeroing.
// grid (32, 12, 16), 256 threads.
// ---------------------------------------------------------------------------
__global__ __launch_bounds__(256, 2) void gemm1_kernel(const float4* __restrict__ Wd,
                                                       float4* __restrict__ out) {
    extern __shared__ char smem[];
    int e = blockIdx.z;
    int cnt = g_counts[e];
    int m0 = blockIdx.x * BM;
    int tid = threadIdx.x;
    if (m0 >= cnt) {                   // idle block -> scavenge side work
        drain_tickets(Wd, out, tid);
        return;
    }
    int n0 = blockIdx.y * 64;

    int* toks = (int*)smem;
    if (tid < BM) {
        int m = m0 + tid;
        toks[tid] = (m < cnt) ? g_tok[e * T_TOK + m] : g_tok[e * T_TOK];
    }
    __syncthreads();

    uint32_t sb1 = smem_u32(smem) + 1024;
    int lrow = tid >> 1, h = tid & 1;
    const char* asrc = (const char*)(g_x16 + (size_t)toks[lrow] * HDIM) + h * 64;
    const char* bsrc = (lrow < 64)
        ? (const char*)(g_wg16 + ((size_t)e * FDIM + n0 + lrow) * HDIM) + h * 64
        : (const char*)(g_wu16 + ((size_t)e * FDIM + n0 + lrow - 64) * HDIM) + h * 64;
    uint32_t adst_off = (uint32_t)(lrow * ROWB + h * 64);

    int wid = tid >> 5, lane = tid & 31;
    int wm = wid & 3, wv = wid >> 2;

    Frag F = {};
    mainloop(smem, sb1, asrc, bsrc, adst_off, HDIM / 64, wm, wv, lane, F);

    // exchange gate/up, SiLU combine, store fp16 act
    __syncthreads();
    float* ex = (float*)(smem + 1024);
    float* eu = ex + 128 * 64;
    float* dbuf = wv ? eu : ex;
    int qr = lane >> 2, qc = lane & 3;
#pragma unroll
    for (int mi = 0; mi < 2; mi++) {
        int r = wm * 32 + mi * 16 + qr;
#pragma unroll
        for (int ni = 0; ni < 8; ni++) {
            int col = ni * 8 + qc * 2;
            *(float2*)&dbuf[r * 64 + col]       = make_float2(F.acc[mi][ni][0], F.acc[mi][ni][1]);
            *(float2*)&dbuf[(r + 8) * 64 + col] = make_float2(F.acc[mi][ni][2], F.acc[mi][ni][3]);
        }
    }
    __syncthreads();

    int r = tid >> 1, hs = tid & 1;
    int m = m0 + r;
    if (m < cnt) {
        float rw = g_w[e * T_TOK + m];
        __half* dst = g_act16 + ((size_t)e * T_TOK + m) * FDIM + n0 + hs * 32;
        const float* gg = ex + r * 64 + hs * 32;
        const float* uu = eu + r * 64 + hs * 32;
#pragma unroll
        for (int j = 0; j < 32; j += 4) {
            float4 g4 = *(const float4*)(gg + j);
            float4 u4 = *(const float4*)(uu + j);
            float4 v;
            v.x = g4.x / (1.0f + expf(-g4.x)) * u4.x * rw;
            v.y = g4.y / (1.0f + expf(-g4.y)) * u4.y * rw;
            v.z = g4.z / (1.0f + expf(-g4.z)) * u4.z * rw;
            v.w = g4.w / (1.0f + expf(-g4.w)) * u4.w * rw;
            cvt_store4(v, dst + j);
        }
    }
    __syncthreads();
    drain_tickets(Wd, out, tid);       // mop up any remaining side work
}

// ---------------------------------------------------------------------------
// GEMM2: out[tok] += act16 @ Wd16^T, BN=128, K=768. grid (32, 16, 16)
// ---------------------------------------------------------------------------
__global__ __launch_bounds__(256, 2) void gemm2_kernel(float* __restrict__ out) {
    extern __shared__ char smem[];
    int e = blockIdx.z;
    int cnt = g_counts[e];
    int m0 = blockIdx.x * BM;
    if (m0 >= cnt) return;
    int n0 = blockIdx.y * 128;
    int tid = threadIdx.x;

    int* toks = (int*)smem;
    if (tid < BM) {
        int m = m0 + tid;
        toks[tid] = (m < cnt) ? g_tok[e * T_TOK + m] : g_tok[e * T_TOK];
    }
    __syncthreads();

    uint32_t sb1 = smem_u32(smem) + 1024;
    int lrow = tid >> 1, h = tid & 1;
    const char* asrc = (const char*)(g_act16 + ((size_t)e * T_TOK + m0 + lrow) * FDIM) + h * 64;
    const char* bsrc = (const char*)(g_wd16 + ((size_t)e * HDIM + n0 + lrow) * FDIM) + h * 64;
    uint32_t adst_off = (uint32_t)(lrow * ROWB + h * 64);

    int wid = tid >> 5, lane = tid & 31;
    int wm = wid & 3, wn = wid >> 2;
    int qr = lane >> 2, qc = lane & 3;

    Frag F = {};
    mainloop(smem, sb1, asrc, bsrc, adst_off, FDIM / 64, wm, wn, lane, F);

    // scatter-add epilogue (f32x2 RED)
#pragma unroll
    for (int mi = 0; mi < 2; mi++) {
#pragma unroll
        for (int rh = 0; rh < 2; rh++) {
            int mrow = wm * 32 + mi * 16 + rh * 8 + qr;
            int m = m0 + mrow;
            if (m < cnt) {
                float* dst = out + (size_t)toks[mrow] * HDIM + n0 + wn * 64;
#pragma unroll
                for (int ni = 0; ni < 8; ni++) {
                    float2 v = make_float2(F.acc[mi][ni][rh * 2 + 0], F.acc[mi][ni][rh * 2 + 1]);
                    atomicAdd(reinterpret_cast<float2*>(dst + ni * 8 + qc * 2), v);
                }
            }
        }
    }
}

// ---------------------------------------------------------------------------
extern "C" void kernel_launch(void* const* d_in, const int* in_sizes, int n_in,
                              void* d_out, int out_size) {
    const float* x  = (const float*)d_in[0];
    const float* Wr = (const float*)d_in[1];
    const float* Wg = (const float*)d_in[2];
    const float* Wu = (const float*)d_in[3];
    const float* Wd = (const float*)d_in[4];
    float* out = (float*)d_out;

    cudaFuncSetAttribute(router_kernel, cudaFuncAttributeMaxDynamicSharedMemorySize, RT_SMEM);
    cudaFuncSetAttribute(gemm1_kernel,  cudaFuncAttributeMaxDynamicSharedMemorySize, SMEM_GEMM);
    cudaFuncSetAttribute(gemm2_kernel,  cudaFuncAttributeMaxDynamicSharedMemorySize, SMEM_GEMM);

    prep_kernel<<<1024, 256>>>((const float4*)Wg, (const float4*)Wu);

    router_kernel<<<T_TOK / RT_TOKS, 256, RT_SMEM>>>(x, Wr);

    dispatch_kernel<<<(T_TOK * TOPK + 255) / 256, 256>>>();

    dim3 g1(T_TOK / BM, FDIM / 64, NEXP);
    gemm1_kernel<<<g1, 256, SMEM_GEMM>>>((const float4*)Wd, (float4*)out);

    dim3 g2(T_TOK / BM, HDIM / 128, NEXP);
    gemm2_kernel<<<g2, 256, SMEM_GEMM>>>(out);
}

// round 15
// speedup vs baseline: 1.4907x; 1.3575x over previous
#include <cuda_runtime.h>
#include <cuda_fp16.h>
#include <cstdint>
#include <math.h>

#define T_TOK 4096
#define HDIM  2048
#define NEXP  16
#define FDIM  768
#define TOPK  4

#define BM    128
#define BN    256                       // B rows per tile
#define ROWB  144                       // 128B data + 16B pad per smem row
#define ATILE (128 * ROWB)              // A region size; B starts here
#define STG   (384 * ROWB)              // 55296 B per stage (A 128 + B 256 rows)
#define NSTG  4
#define SMEM_GEMM (1024 + NSTG * STG)   // 222208 B -> 1 block/SM
#define REX   132                       // exchange row stride (floats, mult of 4)

// ---- scratch (device globals; allocation is forbidden) ----
__device__ int    g_counts[NEXP];
__device__ int    g_tok[NEXP * T_TOK];
__device__ float  g_w[NEXP * T_TOK];
__device__ int    g_eid[T_TOK * TOPK];
__device__ float  g_topw[T_TOK * TOPK];
__device__ __half g_x16[(size_t)T_TOK * HDIM];
__device__ __half g_wg16[(size_t)NEXP * FDIM * HDIM];
__device__ __half g_wu16[(size_t)NEXP * FDIM * HDIM];
__device__ __half g_wd16[(size_t)NEXP * HDIM * FDIM];
__device__ __half g_act16[(size_t)NEXP * T_TOK * FDIM];

// ---------------------------------------------------------------------------
// helpers
// ---------------------------------------------------------------------------
__device__ __forceinline__ uint32_t smem_u32(const void* p) {
    uint32_t a;
    asm("{ .reg .u64 t; cvta.to.shared.u64 t, %1; cvt.u32.u64 %0, t; }" : "=r"(a) : "l"(p));
    return a;
}
__device__ __forceinline__ void cp16(uint32_t smem, const void* g) {
    asm volatile("cp.async.cg.shared.global [%0], [%1], 16;" :: "r"(smem), "l"(g));
}
__device__ __forceinline__ void cp_commit() { asm volatile("cp.async.commit_group;"); }
template <int N>
__device__ __forceinline__ void cp_wait() { asm volatile("cp.async.wait_group %0;" :: "n"(N)); }

#define MMA_F16(C, A0, A1, A2, A3, B0, B1) \
    asm volatile("mma.sync.aligned.m16n8k16.row.col.f32.f16.f16.f32 " \
                 "{%0,%1,%2,%3}, {%4,%5,%6,%7}, {%8,%9}, {%0,%1,%2,%3};" \
                 : "+f"((C)[0]), "+f"((C)[1]), "+f"((C)[2]), "+f"((C)[3]) \
                 : "r"(A0), "r"(A1), "r"(A2), "r"(A3), "r"(B0), "r"(B1))

#define LDSM4(R, addr) \
    asm volatile("ldmatrix.sync.aligned.m8n8.x4.shared.b16 {%0,%1,%2,%3}, [%4];" \
                 : "=r"((R)[0]), "=r"((R)[1]), "=r"((R)[2]), "=r"((R)[3]) : "r"(addr))

__device__ __forceinline__ void cvt_store4(const float4 v, __half* dst) {
    __half2 a = __floats2half2_rn(v.x, v.y);
    __half2 b = __floats2half2_rn(v.z, v.w);
    uint2 u = make_uint2(*(const uint32_t*)&a, *(const uint32_t*)&b);
    *(uint2*)dst = u;
}

// ---------------------------------------------------------------------------
// prep: fp32 -> fp16 for Wg/Wu/Wd; zero out; zero counts
// ---------------------------------------------------------------------------
__global__ void prep_kernel(const float4* __restrict__ Wg,
                            const float4* __restrict__ Wu,
                            const float4* __restrict__ Wd,
                            float4* __restrict__ out) {
    size_t i0 = (size_t)blockIdx.x * blockDim.x + threadIdx.x;
    size_t st = (size_t)gridDim.x * blockDim.x;
    const size_t nx4 = (size_t)T_TOK * HDIM / 4;
    const size_t nw4 = (size_t)NEXP * FDIM * HDIM / 4;
    const float4 z = make_float4(0.f, 0.f, 0.f, 0.f);
    for (size_t i = i0; i < nx4; i += st) out[i] = z;
    for (size_t i = i0; i < nw4; i += st) {
        cvt_store4(Wg[i], g_wg16 + 4 * i);
        cvt_store4(Wu[i], g_wu16 + 4 * i);
        cvt_store4(Wd[i], g_wd16 + 4 * i);
    }
    if (i0 < NEXP) g_counts[i0] = 0;
}

// ---------------------------------------------------------------------------
// Router: 16 tokens/block; also emits fp16 copy of x.
// ---------------------------------------------------------------------------
#define RT_TOKS 16
#define RT_PAD  2052
#define RT_SMEM ((RT_TOKS * RT_PAD + RT_TOKS * NEXP) * 4)

__global__ __launch_bounds__(256) void router_kernel(const float* __restrict__ x,
                                                     const float* __restrict__ Wr) {
    extern __shared__ float rs[];
    float* xs = rs;
    float* lg = rs + RT_TOKS * RT_PAD;
    int tid = threadIdx.x;
    int tok0 = blockIdx.x * RT_TOKS;

    for (int idx = tid; idx < RT_TOKS * HDIM; idx += 256) {
        int t = idx >> 11, k = idx & (HDIM - 1);
        xs[t * RT_PAD + k] = x[(size_t)(tok0 + t) * HDIM + k];
    }
    __syncthreads();

    for (int idx = tid * 4; idx < RT_TOKS * HDIM; idx += 256 * 4) {
        int t = idx >> 11, k = idx & (HDIM - 1);
        float4 v = *(const float4*)(xs + t * RT_PAD + k);
        cvt_store4(v, g_x16 + (size_t)(tok0 + t) * HDIM + k);
    }

    int t = tid & 15, e = tid >> 4;
    const float* wr = Wr + (size_t)e * HDIM;
    const float* xr = xs + t * RT_PAD;
    float acc = 0.0f;
#pragma unroll 8
    for (int k = 0; k < HDIM; k++) acc += xr[k] * wr[k];
    lg[t * NEXP + e] = acc;
    __syncthreads();

    if (tid < RT_TOKS) {
        int tt = tok0 + tid;
        const float* l = lg + tid * NEXP;
        float m = l[0];
#pragma unroll
        for (int i = 1; i < NEXP; i++) m = fmaxf(m, l[i]);
        float p[NEXP]; float s = 0.0f;
#pragma unroll
        for (int i = 0; i < NEXP; i++) { p[i] = expf(l[i] - m); s += p[i]; }
        float inv_s = 1.0f / s;
        bool used[NEXP];
#pragma unroll
        for (int i = 0; i < NEXP; i++) used[i] = false;
        int ids[TOPK]; float ws[TOPK]; float wsum = 0.0f;
#pragma unroll
        for (int k = 0; k < TOPK; k++) {
            int bi = -1; float bv = -1.0f;
#pragma unroll
            for (int i = 0; i < NEXP; i++)
                if (!used[i] && p[i] > bv) { bv = p[i]; bi = i; }
            used[bi] = true;
            ids[k] = bi; ws[k] = bv * inv_s; wsum += ws[k];
        }
        float inv_w = 1.0f / wsum;
#pragma unroll
        for (int k = 0; k < TOPK; k++) {
            g_eid[tt * TOPK + k]  = ids[k];
            g_topw[tt * TOPK + k] = ws[k] * inv_w;
        }
    }
}

__global__ void dispatch_kernel() {
    int i = blockIdx.x * blockDim.x + threadIdx.x;
    if (i >= T_TOK * TOPK) return;
    int e = g_eid[i];
    int pos = atomicAdd(&g_counts[e], 1);
    g_tok[e * T_TOK + pos] = i >> 2;
    g_w[e * T_TOK + pos]   = g_topw[i];
}

// ---------------------------------------------------------------------------
// Mainloop: BM=128, BN=256, BK=64 halves (128B rows). 512 threads, 16 warps
// of 32x64. 4-stage cp.async ring; per iter: issue(it+2) -> commit ->
// wait<2> -> barrier -> compute(it). Stage being computed was committed two
// iterations ago (full stage of latency slack); writer stage (it+2)%4 vs
// slowest reader (it-1)%4 differ by 3 mod 4 -> no hazard.
// Per thread per stage: 6 x cp16 (one 16B column chunk at rows r0+64k).
// ---------------------------------------------------------------------------
struct Frag { float acc[2][8][4]; };

__device__ __forceinline__ void mainloop(uint32_t sb1,
                                         const char* asrc0, const char* asrc1,
                                         const char* bsrc0, const char* bsrc1,
                                         uint32_t RS, uint32_t dstb, int NIT,
                                         int wm, int wc, int lane, Frag& F) {
    auto issue = [&](int s, int kb) {
        uint32_t d0 = sb1 + s * STG + dstb;
        cp16(d0,              asrc0 + kb);
        cp16(d0 +  64 * ROWB, asrc1 + kb);
        cp16(d0 + 128 * ROWB, bsrc0 + kb);
        cp16(d0 + 192 * ROWB, bsrc0 + 64 * RS + kb);
        cp16(d0 + 256 * ROWB, bsrc1 + kb);
        cp16(d0 + 320 * ROWB, bsrc1 + 64 * RS + kb);
    };

    uint32_t a_lane = (uint32_t)((lane & 15) * ROWB + (lane >> 4) * 16);
    uint32_t b_lane = (uint32_t)(((lane >> 4) * 8 + (lane & 7)) * ROWB + ((lane >> 3) & 1) * 16);
    uint32_t aoff0 = (uint32_t)(wm * 32 * ROWB) + a_lane;
    uint32_t aoff1 = aoff0 + 16 * ROWB;
    uint32_t boff  = ATILE + (uint32_t)(wc * 64 * ROWB) + b_lane;

    issue(0, 0);   cp_commit();
    issue(1, 128); cp_commit();

    for (int it = 0; it < NIT; ++it) {
        int pf = it + 2;
        if (pf < NIT) issue(pf & 3, pf * 128);
        cp_commit();
        cp_wait<2>();
        __syncthreads();

        uint32_t base = sb1 + (it & 3) * STG;
#pragma unroll
        for (int ks = 0; ks < 4; ks++) {
            uint32_t ko = ks * 32;
            uint32_t a0[4], a1[4];
            LDSM4(a0, base + aoff0 + ko);
            LDSM4(a1, base + aoff1 + ko);
#pragma unroll
            for (int np = 0; np < 4; np++) {
                uint32_t b[4];
                LDSM4(b, base + boff + np * (16 * ROWB) + ko);
                MMA_F16(F.acc[0][2 * np],     a0[0], a0[1], a0[2], a0[3], b[0], b[1]);
                MMA_F16(F.acc[0][2 * np + 1], a0[0], a0[1], a0[2], a0[3], b[2], b[3]);
                MMA_F16(F.acc[1][2 * np],     a1[0], a1[1], a1[2], a1[3], b[0], b[1]);
                MMA_F16(F.acc[1][2 * np + 1], a1[0], a1[1], a1[2], a1[3], b[2], b[3]);
            }
        }
    }
}

// ---------------------------------------------------------------------------
// GEMM1: 128 gate cols + 128 up cols per block. grid (32, 6, 16), 512 thr.
// ---------------------------------------------------------------------------
__global__ __launch_bounds__(512, 1) void gemm1_kernel() {
    extern __shared__ char smem[];
    int e = blockIdx.z;
    int cnt = g_counts[e];
    int m0 = blockIdx.x * BM;
    if (m0 >= cnt) return;
    int n0 = blockIdx.y * 128;
    int tid = threadIdx.x;

    int* toks = (int*)smem;
    if (tid < BM) {
        int m = m0 + tid;
        toks[tid] = (m < cnt) ? g_tok[e * T_TOK + m] : g_tok[e * T_TOK];
    }
    __syncthreads();

    uint32_t sb1 = smem_u32(smem) + 1024;
    int r = tid >> 3, c = tid & 7;
    const char* asrc0 = (const char*)(g_x16 + (size_t)toks[r] * HDIM) + c * 16;
    const char* asrc1 = (const char*)(g_x16 + (size_t)toks[r + 64] * HDIM) + c * 16;
    const char* bsrc0 = (const char*)(g_wg16 + ((size_t)e * FDIM + n0 + r) * HDIM) + c * 16;
    const char* bsrc1 = (const char*)(g_wu16 + ((size_t)e * FDIM + n0 + r) * HDIM) + c * 16;
    uint32_t dstb = (uint32_t)(r * ROWB + c * 16);

    int wid = tid >> 5, lane = tid & 31;
    int wm = wid & 3, wc = wid >> 2;          // wc 0,1 = gate; 2,3 = up

    Frag F = {};
    mainloop(sb1, asrc0, asrc1, bsrc0, bsrc1, HDIM * 2, dstb,
             HDIM * 2 / 128, wm, wc, lane, F);

    // exchange gate/up halves, SiLU combine, store fp16 act
    __syncthreads();
    float* ex = (float*)(smem + 1024);
    float* eu = ex + 128 * REX;
    float* dbuf = (wc < 2) ? ex : eu;
    int cb0 = (wc & 1) * 64;
    int qr = lane >> 2, qc = lane & 3;
#pragma unroll
    for (int mi = 0; mi < 2; mi++) {
        int rr = wm * 32 + mi * 16 + qr;
#pragma unroll
        for (int ni = 0; ni < 8; ni++) {
            int col = cb0 + ni * 8 + qc * 2;
            *(float2*)&dbuf[rr * REX + col]       = make_float2(F.acc[mi][ni][0], F.acc[mi][ni][1]);
            *(float2*)&dbuf[(rr + 8) * REX + col] = make_float2(F.acc[mi][ni][2], F.acc[mi][ni][3]);
        }
    }
    __syncthreads();

    int rr = tid >> 2, cb = (tid & 3) * 32;
    int m = m0 + rr;
    if (m < cnt) {
        float rw = g_w[e * T_TOK + m];
        __half* dst = g_act16 + ((size_t)e * T_TOK + m) * FDIM + n0 + cb;
        const float* gg = ex + rr * REX + cb;
        const float* uu = eu + rr * REX + cb;
#pragma unroll
        for (int j = 0; j < 32; j += 4) {
            float4 g4 = *(const float4*)(gg + j);
            float4 u4 = *(const float4*)(uu + j);
            float4 v;
            v.x = g4.x / (1.0f + expf(-g4.x)) * u4.x * rw;
            v.y = g4.y / (1.0f + expf(-g4.y)) * u4.y * rw;
            v.z = g4.z / (1.0f + expf(-g4.z)) * u4.z * rw;
            v.w = g4.w / (1.0f + expf(-g4.w)) * u4.w * rw;
            cvt_store4(v, dst + j);
        }
    }
}

// ---------------------------------------------------------------------------
// GEMM2: out[tok] += act16 @ Wd16^T, BN=256, K=768. grid (32, 8, 16), 512 thr.
// ---------------------------------------------------------------------------
__global__ __launch_bounds__(512, 1) void gemm2_kernel(float* __restrict__ out) {
    extern __shared__ char smem[];
    int e = blockIdx.z;
    int cnt = g_counts[e];
    int m0 = blockIdx.x * BM;
    if (m0 >= cnt) return;
    int n0 = blockIdx.y * BN;
    int tid = threadIdx.x;

    int* toks = (int*)smem;
    if (tid < BM) {
        int m = m0 + tid;
        toks[tid] = (m < cnt) ? g_tok[e * T_TOK + m] : g_tok[e * T_TOK];
    }
    __syncthreads();

    uint32_t sb1 = smem_u32(smem) + 1024;
    int r = tid >> 3, c = tid & 7;
    const char* asrc0 = (const char*)(g_act16 + ((size_t)e * T_TOK + m0 + r) * FDIM) + c * 16;
    const char* asrc1 = asrc0 + (size_t)64 * FDIM * 2;
    const char* bsrc0 = (const char*)(g_wd16 + ((size_t)e * HDIM + n0 + r) * FDIM) + c * 16;
    const char* bsrc1 = bsrc0 + (size_t)128 * FDIM * 2;
    uint32_t dstb = (uint32_t)(r * ROWB + c * 16);

    int wid = tid >> 5, lane = tid & 31;
    int wm = wid & 3, wn = wid >> 2;
    int qr = lane >> 2, qc = lane & 3;

    Frag F = {};
    mainloop(sb1, asrc0, asrc1, bsrc0, bsrc1, FDIM * 2, dstb,
             FDIM * 2 / 128, wm, wn, lane, F);

    // scatter-add epilogue (f32x2 RED)
#pragma unroll
    for (int mi = 0; mi < 2; mi++) {
#pragma unroll
        for (int rh = 0; rh < 2; rh++) {
            int mrow = wm * 32 + mi * 16 + rh * 8 + qr;
            int m = m0 + mrow;
            if (m < cnt) {
                float* dst = out + (size_t)toks[mrow] * HDIM + n0 + wn * 64;
#pragma unroll
                for (int ni = 0; ni < 8; ni++) {
                    float2 v = make_float2(F.acc[mi][ni][rh * 2 + 0], F.acc[mi][ni][rh * 2 + 1]);
                    atomicAdd(reinterpret_cast<float2*>(dst + ni * 8 + qc * 2), v);
                }
            }
        }
    }
}

// ---------------------------------------------------------------------------
extern "C" void kernel_launch(void* const* d_in, const int* in_sizes, int n_in,
                              void* d_out, int out_size) {
    const float* x  = (const float*)d_in[0];
    const float* Wr = (const float*)d_in[1];
    const float* Wg = (const float*)d_in[2];
    const float* Wu = (const float*)d_in[3];
    const float* Wd = (const float*)d_in[4];
    float* out = (float*)d_out;

    cudaFuncSetAttribute(router_kernel, cudaFuncAttributeMaxDynamicSharedMemorySize, RT_SMEM);
    cudaFuncSetAttribute(gemm1_kernel,  cudaFuncAttributeMaxDynamicSharedMemorySize, SMEM_GEMM);
    cudaFuncSetAttribute(gemm2_kernel,  cudaFuncAttributeMaxDynamicSharedMemorySize, SMEM_GEMM);

    prep_kernel<<<1024, 256>>>((const float4*)Wg, (const float4*)Wu,
                               (const float4*)Wd, (float4*)out);

    router_kernel<<<T_TOK / RT_TOKS, 256, RT_SMEM>>>(x, Wr);

    dispatch_kernel<<<(T_TOK * TOPK + 255) / 256, 256>>>();

    dim3 g1(T_TOK / BM, FDIM / 128, NEXP);
    gemm1_kernel<<<g1, 512, SMEM_GEMM>>>();

    dim3 g2(T_TOK / BM, HDIM / BN, NEXP);
    gemm2_kernel<<<g2, 512, SMEM_GEMM>>>(out);
}